// round 7
// baseline (speedup 1.0000x reference)
#include <cuda_runtime.h>
#include <math.h>
#include <stdint.h>

// ---------------- problem dims ----------------
#define B2   2
#define S48  110592   // 48^3
#define S24  13824    // 24^3
#define S12  1728     // 12^3
#define EE   768
#define NH   12
#define HD   64
#define NTOK (B2*S12)     // 3456
#define KK2  1536         // conv2 inner dim (192*8)
#define NPATCH (B2*S24)   // 27648 patch rows (= NTOK*8)

// ---------------- scratch (__device__ globals; no runtime alloc) ----------------
__device__ float g_patchs[NPATCH*48];
__device__ float g_patchx[NPATCH*48];
__device__ float g_h1b   [NPATCH*192];           // conv1 out == conv2 A [3456x1536]
__device__ float g_q     [NTOK*EE];
__device__ float g_k     [NTOK*EE];
__device__ float g_v     [NTOK*EE];
__device__ float g_Wt    [KK2*EE];               // transposed weight scratch (reused)
__device__ float g_att   [NTOK*EE];
__device__ float g_deb   [NTOK*KK2];

// ---------------- block reductions ----------------
__device__ __forceinline__ float blk_sum(float v, float* sh) {
    int lane = threadIdx.x & 31;
#pragma unroll
    for (int o = 16; o; o >>= 1) v += __shfl_xor_sync(0xffffffffu, v, o);
    __syncthreads();
    if (lane == 0) sh[threadIdx.x >> 5] = v;
    __syncthreads();
    int nw = blockDim.x >> 5;
    v = (lane < nw) ? sh[lane] : 0.f;
#pragma unroll
    for (int o = 16; o; o >>= 1) v += __shfl_xor_sync(0xffffffffu, v, o);
    return v;
}

// robust fp32 sincos: Cody-Waite reduce mod 2pi, then accurate-range trig.
__device__ __forceinline__ void rope_trig(float f, float& cs, float& sn) {
    float n = rintf(f * 0.15915494309189535f);
    float r = fmaf(-n, 6.28125f, f);
    r = fmaf(-n, 1.9353071795864769e-3f, r);
    cs = cosf(r);
    sn = sinf(r);
}

// ---------------- tf32 split helpers ----------------
__device__ __forceinline__ void split_tf32(float x, float& hi, float& lo) {
    uint32_t h, l;
    asm("cvt.rna.tf32.f32 %0, %1;" : "=r"(h) : "f"(x));
    float hf = __uint_as_float(h);
    asm("cvt.rna.tf32.f32 %0, %1;" : "=r"(l) : "f"(x - hf));
    hi = hf;
    lo = __uint_as_float(l);
}
__device__ __forceinline__ void mma_tf32(float* c, const uint32_t* a, const uint32_t* b) {
    asm volatile(
        "mma.sync.aligned.m16n8k8.row.col.f32.tf32.tf32.f32 "
        "{%0,%1,%2,%3}, {%4,%5,%6,%7}, {%8,%9}, {%0,%1,%2,%3};\n"
        : "+f"(c[0]), "+f"(c[1]), "+f"(c[2]), "+f"(c[3])
        : "r"(a[0]), "r"(a[1]), "r"(a[2]), "r"(a[3]), "r"(b[0]), "r"(b[1]));
}

// ---------------- fused LN6 + patch gather ----------------
__global__ void k_patch(const float* __restrict__ in, const float* __restrict__ w,
                        const float* __restrict__ bb, float* __restrict__ out) {
    int id = blockIdx.x * blockDim.x + threadIdx.x;
    if (id >= NPATCH * 8) return;
    int kpq = id & 7;
    int p = id >> 3;
    int bn = p / S24, pos = p - bn * S24;
    int h = pos / 576, w24 = (pos / 24) % 24, d = pos % 24;
    int k = kpq >> 2, pp = (kpq >> 1) & 1, qq = kpq & 1;
    size_t sp = ((size_t)(2 * h + k) * 48 + 2 * w24 + pp) * 48 + 2 * d + qq;
    const float* base = in + (size_t)bn * 6 * S48 + sp;
    float v[6], u = 0.f;
#pragma unroll
    for (int c = 0; c < 6; c++) { v[c] = base[(size_t)c * S48]; u += v[c]; }
    u *= (1.f / 6.f);
    float s = 0.f;
#pragma unroll
    for (int c = 0; c < 6; c++) { float dd = v[c] - u; s += dd * dd; }
    s *= (1.f / 6.f);
    float r = rsqrtf(s + 1e-6f);
    int token = bn * S12 + (h >> 1) * 144 + (w24 >> 1) * 12 + (d >> 1);
    int par = (h & 1) * 4 + (w24 & 1) * 2 + (d & 1);
    float* ob = out + ((size_t)token * 8 + par) * 48 + kpq;
#pragma unroll
    for (int c = 0; c < 6; c++) ob[c * 8] = (v[c] - u) * r * w[c] + bb[c];
}

// ---------------- small SGEMM (conv1 only): 64x64 tile ----------------
__global__ void k_gemm64(const float* __restrict__ A, const float* __restrict__ B,
                         float* __restrict__ C, int K, int lda, int ldb, int ldc) {
    __shared__ float As[16][64];
    __shared__ float Bs[16][64];
    int tid = threadIdx.x;
    int tx = tid & 15, ty = tid >> 4;
    int n0 = blockIdx.y * 64, m0 = blockIdx.x * 64;
    int lr = tid >> 2, lc = (tid & 3) * 4;
    int br = tid >> 4, bc = (tid & 15) * 4;
    const float* Ap = A + (size_t)(n0 + lr) * lda + lc;
    const float* Bp = B + (size_t)br * ldb + m0 + bc;
    float acc[4][4] = {};
    for (int k0 = 0; k0 < K; k0 += 16) {
        float4 a  = *(const float4*)(Ap + k0);
        float4 bv = *(const float4*)(Bp + (size_t)k0 * ldb);
        __syncthreads();
        As[lc + 0][lr] = a.x; As[lc + 1][lr] = a.y; As[lc + 2][lr] = a.z; As[lc + 3][lr] = a.w;
        *(float4*)&Bs[br][bc] = bv;
        __syncthreads();
#pragma unroll
        for (int kk = 0; kk < 16; kk++) {
            float4 av = *(const float4*)&As[kk][ty * 4];
            float4 bw = *(const float4*)&Bs[kk][tx * 4];
            float aa[4] = {av.x, av.y, av.z, av.w};
            float bbv[4] = {bw.x, bw.y, bw.z, bw.w};
#pragma unroll
            for (int i = 0; i < 4; i++)
#pragma unroll
                for (int j = 0; j < 4; j++) acc[i][j] += aa[i] * bbv[j];
        }
    }
#pragma unroll
    for (int i = 0; i < 4; i++) {
        float4 o = make_float4(acc[i][0], acc[i][1], acc[i][2], acc[i][3]);
        *(float4*)&C[(size_t)(n0 + ty * 4 + i) * ldc + m0 + tx * 4] = o;
    }
}

// ---------------- 3xTF32 tensor-core GEMM: C[n][m] = sum_k A[n][k]*B[k][m] ----------------
// block: 256 thr, tile 64(rows) x 128(cols), k-step 16; warp tile 32x32.
// requires rows%64==0, cols%128==0, K%16==0.
#define AS_STR 20
#define BS_STR 136
__global__ __launch_bounds__(256, 2)
void k_mma_tf32(const float* __restrict__ A, const float* __restrict__ B,
                float* __restrict__ C, int K, int lda, int ldb, int ldc) {
    __shared__ float Ah[64 * AS_STR], Al[64 * AS_STR];
    __shared__ float Bh[16 * BS_STR], Bl[16 * BS_STR];
    int tid = threadIdx.x;
    int warp = tid >> 5, lane = tid & 31;
    int n0 = blockIdx.y * 64;
    int m0 = blockIdx.x * 128;
    int wm = (warp >> 2) * 32;      // warp row offset (0 or 32)
    int wn = (warp & 3) * 32;       // warp col offset (0..96)
    int ar = tid >> 2, ac = (tid & 3) * 4;   // A loader: 64 rows x 16 k
    int bk = tid >> 4, bm = (tid & 15) * 8;  // B loader: 16 k x 128 m

    float acc[2][4][4] = {};

    for (int k0 = 0; k0 < K; k0 += 16) {
        __syncthreads();
        {
            float4 a = *(const float4*)&A[(size_t)(n0 + ar) * lda + k0 + ac];
            float av[4] = {a.x, a.y, a.z, a.w};
#pragma unroll
            for (int i = 0; i < 4; i++) {
                float h, l;
                split_tf32(av[i], h, l);
                Ah[ar * AS_STR + ac + i] = h;
                Al[ar * AS_STR + ac + i] = l;
            }
#pragma unroll
            for (int half = 0; half < 2; half++) {
                float4 b = *(const float4*)&B[(size_t)(k0 + bk) * ldb + m0 + bm + half * 4];
                float bv[4] = {b.x, b.y, b.z, b.w};
#pragma unroll
                for (int i = 0; i < 4; i++) {
                    float h, l;
                    split_tf32(bv[i], h, l);
                    Bh[bk * BS_STR + bm + half * 4 + i] = h;
                    Bl[bk * BS_STR + bm + half * 4 + i] = l;
                }
            }
        }
        __syncthreads();

#pragma unroll
        for (int kk = 0; kk < 16; kk += 8) {
            uint32_t a_h[2][4], a_l[2][4];
            int ar0 = wm + (lane >> 2);
            int ak = kk + (lane & 3);
#pragma unroll
            for (int ma = 0; ma < 2; ma++) {
                int r = ar0 + ma * 16;
                a_h[ma][0] = __float_as_uint(Ah[r * AS_STR + ak]);
                a_h[ma][1] = __float_as_uint(Ah[(r + 8) * AS_STR + ak]);
                a_h[ma][2] = __float_as_uint(Ah[r * AS_STR + ak + 4]);
                a_h[ma][3] = __float_as_uint(Ah[(r + 8) * AS_STR + ak + 4]);
                a_l[ma][0] = __float_as_uint(Al[r * AS_STR + ak]);
                a_l[ma][1] = __float_as_uint(Al[(r + 8) * AS_STR + ak]);
                a_l[ma][2] = __float_as_uint(Al[r * AS_STR + ak + 4]);
                a_l[ma][3] = __float_as_uint(Al[(r + 8) * AS_STR + ak + 4]);
            }
            uint32_t b_h[4][2], b_l[4][2];
            int bk0 = kk + (lane & 3);
#pragma unroll
            for (int na = 0; na < 4; na++) {
                int bc = wn + na * 8 + (lane >> 2);
                b_h[na][0] = __float_as_uint(Bh[bk0 * BS_STR + bc]);
                b_h[na][1] = __float_as_uint(Bh[(bk0 + 4) * BS_STR + bc]);
                b_l[na][0] = __float_as_uint(Bl[bk0 * BS_STR + bc]);
                b_l[na][1] = __float_as_uint(Bl[(bk0 + 4) * BS_STR + bc]);
            }
#pragma unroll
            for (int ma = 0; ma < 2; ma++)
#pragma unroll
                for (int na = 0; na < 4; na++) {
                    mma_tf32(acc[ma][na], a_h[ma], b_h[na]);
                    mma_tf32(acc[ma][na], a_h[ma], b_l[na]);
                    mma_tf32(acc[ma][na], a_l[ma], b_h[na]);
                }
        }
    }

#pragma unroll
    for (int ma = 0; ma < 2; ma++) {
        int row = n0 + wm + ma * 16 + (lane >> 2);
#pragma unroll
        for (int na = 0; na < 4; na++) {
            int col = m0 + wn + na * 8 + (lane & 3) * 2;
            C[(size_t)row * ldc + col]           = acc[ma][na][0];
            C[(size_t)row * ldc + col + 1]       = acc[ma][na][1];
            C[(size_t)(row + 8) * ldc + col]     = acc[ma][na][2];
            C[(size_t)(row + 8) * ldc + col + 1] = acc[ma][na][3];
        }
    }
}

// ---------------- LN over 768 (+optional RoPE), in place ----------------
__global__ void k_ln768(float* __restrict__ X, const float* __restrict__ w,
                        const float* __restrict__ bb, int doRope) {
    __shared__ float s[768];
    __shared__ float sh[32];
    int n = blockIdx.x, tid = threadIdx.x;
    float* row = X + (size_t)n * 768;
    float partial = 0.f;
#pragma unroll
    for (int it = 0; it < 3; it++) { int j = tid + it * 256; float v = row[j]; s[j] = v; partial += v; }
    float u = blk_sum(partial, sh) * (1.f / 768.f);
    float p2 = 0.f;
#pragma unroll
    for (int it = 0; it < 3; it++) { int j = tid + it * 256; float dd = s[j] - u; p2 += dd * dd; }
    float var = blk_sum(p2, sh) * (1.f / 768.f);
    float rinv = rsqrtf(var + 1e-6f);
#pragma unroll
    for (int it = 0; it < 3; it++) { int j = tid + it * 256; s[j] = (s[j] - u) * rinv * w[j] + bb[j]; }
    __syncthreads();
    if (doRope) {
        int l = n % S12;
#pragma unroll
        for (int it = 0; it < 3; it++) {
            int j = tid + it * 256;
            int jm = (j < 384) ? j : j - 384;
            float inv = exp2f(-(float)jm * (13.287712379549449f / 384.f));
            float f = (float)l * inv;
            float cs, sn;
            rope_trig(f, cs, sn);
            float rot = (j < 384) ? -s[j + 384] : s[j - 384];
            row[j] = s[j] * cs + rot * sn;
        }
    } else {
#pragma unroll
        for (int it = 0; it < 3; it++) { int j = tid + it * 256; row[j] = s[j]; }
    }
}

// ---------------- flash attention: fused scores+softmax+PV ----------------
#define FA_PAD 68
__global__ __launch_bounds__(256, 3)
void k_flash(const float* __restrict__ Q, const float* __restrict__ Km,
             const float* __restrict__ V, float* __restrict__ O) {
    extern __shared__ float smem[];
    float* Qs = smem;                    // [64][FA_PAD] layout [d][r]
    float* Ks = Qs + 64 * FA_PAD;        // [64][FA_PAD] layout [d][c]
    float* Vs = Ks + 64 * FA_PAD;        // [64][FA_PAD] layout [j][d]
    float* Ps = Vs + 64 * FA_PAD;        // [64][FA_PAD] layout [r][j]

    int z = blockIdx.y, b = z / NH, h = z - b * NH;
    int i0 = blockIdx.x * 64;
    const float* qb = Q + (size_t)b * S12 * EE + h * HD;
    const float* kb = Km + (size_t)b * S12 * EE + h * HD;
    const float* vb = V + (size_t)b * S12 * EE + h * HD;

    int tid = threadIdx.x;
    int tx = tid & 15, ty = tid >> 4;
    int lr = tid & 63, lg = tid >> 6;

#pragma unroll
    for (int v4 = 0; v4 < 4; v4++) {
        int d = lg * 16 + v4 * 4;
        float4 qv = *(const float4*)&qb[(size_t)(i0 + lr) * EE + d];
        Qs[(d + 0) * FA_PAD + lr] = qv.x * 0.125f;
        Qs[(d + 1) * FA_PAD + lr] = qv.y * 0.125f;
        Qs[(d + 2) * FA_PAD + lr] = qv.z * 0.125f;
        Qs[(d + 3) * FA_PAD + lr] = qv.w * 0.125f;
    }

    float o[4][4] = {};
    float m[4] = {-3.4e38f, -3.4e38f, -3.4e38f, -3.4e38f};
    float l[4] = {};

    for (int j0 = 0; j0 < S12; j0 += 64) {
        __syncthreads();
#pragma unroll
        for (int v4 = 0; v4 < 4; v4++) {
            int d = lg * 16 + v4 * 4;
            float4 kv = *(const float4*)&kb[(size_t)(j0 + lr) * EE + d];
            Ks[(d + 0) * FA_PAD + lr] = kv.x;
            Ks[(d + 1) * FA_PAD + lr] = kv.y;
            Ks[(d + 2) * FA_PAD + lr] = kv.z;
            Ks[(d + 3) * FA_PAD + lr] = kv.w;
            float4 vv = *(const float4*)&vb[(size_t)(j0 + lr) * EE + d];
            *(float4*)&Vs[lr * FA_PAD + d] = vv;
        }
        __syncthreads();

        float sc[4][4] = {};
#pragma unroll 8
        for (int d = 0; d < 64; d++) {
            float4 qa = *(const float4*)&Qs[d * FA_PAD + ty * 4];
            float4 kbv = *(const float4*)&Ks[d * FA_PAD + tx * 4];
            float a[4] = {qa.x, qa.y, qa.z, qa.w};
            float bb4[4] = {kbv.x, kbv.y, kbv.z, kbv.w};
#pragma unroll
            for (int i = 0; i < 4; i++)
#pragma unroll
                for (int j = 0; j < 4; j++) sc[i][j] = fmaf(a[i], bb4[j], sc[i][j]);
        }

#pragma unroll
        for (int i = 0; i < 4; i++) {
            float rm = fmaxf(fmaxf(sc[i][0], sc[i][1]), fmaxf(sc[i][2], sc[i][3]));
#pragma unroll
            for (int ofs = 8; ofs; ofs >>= 1)
                rm = fmaxf(rm, __shfl_xor_sync(0xffffffffu, rm, ofs));
            float mn = fmaxf(m[i], rm);
            float alpha = expf(m[i] - mn);
            m[i] = mn;
            float rs = 0.f;
#pragma unroll
            for (int j = 0; j < 4; j++) {
                sc[i][j] = expf(sc[i][j] - mn);
                rs += sc[i][j];
            }
#pragma unroll
            for (int ofs = 8; ofs; ofs >>= 1)
                rs += __shfl_xor_sync(0xffffffffu, rs, ofs);
            l[i] = l[i] * alpha + rs;
#pragma unroll
            for (int j = 0; j < 4; j++) o[i][j] *= alpha;
            *(float4*)&Ps[(ty * 4 + i) * FA_PAD + tx * 4] =
                make_float4(sc[i][0], sc[i][1], sc[i][2], sc[i][3]);
        }
        __syncthreads();

#pragma unroll 8
        for (int j = 0; j < 64; j++) {
            float4 vv = *(const float4*)&Vs[j * FA_PAD + tx * 4];
            float bv[4] = {vv.x, vv.y, vv.z, vv.w};
            float a[4];
#pragma unroll
            for (int i = 0; i < 4; i++) a[i] = Ps[(ty * 4 + i) * FA_PAD + j];
#pragma unroll
            for (int i = 0; i < 4; i++)
#pragma unroll
                for (int jj = 0; jj < 4; jj++) o[i][jj] = fmaf(a[i], bv[jj], o[i][jj]);
        }
    }

#pragma unroll
    for (int i = 0; i < 4; i++) {
        float inv = 1.f / l[i];
        float* orow = O + (size_t)(b * S12 + i0 + ty * 4 + i) * EE + h;
#pragma unroll
        for (int jj = 0; jj < 4; jj++)
            orow[(tx * 4 + jj) * NH] = o[i][jj] * inv;
    }
}

// ---------------- weight transposes ----------------
__global__ void k_transW1(const float* __restrict__ in, float* __restrict__ out) {
    int idx = blockIdx.x * blockDim.x + threadIdx.x;
    if (idx >= 192 * 48) return;
    int t = idx / 48, j = idx - t * 48;
    out[j * 192 + t] = in[idx];
}
__global__ void k_transW2(const float* __restrict__ in, float* __restrict__ out) {
    int idx = blockIdx.x * blockDim.x + threadIdx.x;
    if (idx >= EE * KK2) return;
    int o = idx / KK2, rest = idx - o * KK2;
    int t = rest >> 3, par = rest & 7;
    out[(size_t)(par * 192 + t) * EE + o] = in[idx];
}
__global__ void k_transWd(const float* __restrict__ in, float* __restrict__ out) {
    int idx = blockIdx.x * blockDim.x + threadIdx.x;
    if (idx >= EE * KK2) return;
    int i = idx / KK2, rest = idx - i * KK2;
    int o = rest >> 3, r = rest & 7;
    out[(size_t)i * KK2 + r * 192 + o] = in[idx];
}

// ---------------- LN192 + GELU rowwise, in place ----------------
__global__ void k_ln192gelu(float* __restrict__ X, const float* __restrict__ g,
                            const float* __restrict__ bb) {
    __shared__ float sh[32];
    int n = blockIdx.x, t = threadIdx.x;
    float* row = X + (size_t)n * 192;
    float v = row[t];
    float u = blk_sum(v, sh) * (1.f / 192.f);
    float dd = v - u;
    float var = blk_sum(dd * dd, sh) * (1.f / 192.f);
    float xn = dd * rsqrtf(var + 1e-6f) * g[t] + bb[t];
    row[t] = xn * normcdff(xn);
}

// ---------------- final convT2s2 (192->6) + bias + residual ----------------
__global__ void k_debed2(const float* __restrict__ glo, const float* __restrict__ W,
                         const float* __restrict__ bias, const float* __restrict__ res,
                         float* __restrict__ out) {
    __shared__ float row[192];
    int bid = blockIdx.x;
    int bn = bid / S24, pos = bid - bn * S24;
    int H = pos / 576, Wp = (pos / 24) % 24, D = pos % 24;
    int n1 = (H >> 1) * 144 + (Wp >> 1) * 12 + (D >> 1);
    int rr = (H & 1) * 4 + (Wp & 1) * 2 + (D & 1);
    const float* rp = glo + (size_t)(bn * S12 + n1) * KK2 + rr * 192;
    int t = threadIdx.x;
    for (int j = t; j < 192; j += 64) row[j] = rp[j];
    __syncthreads();
    if (t < 48) {
        int c = t >> 3, r2 = t & 7;
        float acc = 0.f;
#pragma unroll
        for (int o = 0; o < 192; o++) acc += row[o] * __ldg(&W[o * 48 + c * 8 + r2]);
        int Hf = 2 * H + (r2 >> 2), Wf = 2 * Wp + ((r2 >> 1) & 1), Df = 2 * D + (r2 & 1);
        size_t oi = (((size_t)(bn * 6 + c) * 48 + Hf) * 48 + Wf) * 48 + Df;
        out[oi] = acc + bias[c] + res[oi];
    }
}

// ---------------- launch ----------------
extern "C" void kernel_launch(void* const* d_in, const int* in_sizes, int n_in,
                              void* d_out, int out_size) {
    const float* x     = (const float*)d_in[0];
    const float* skip  = (const float*)d_in[1];
    const float* o_tw1 = (const float*)d_in[20];
    const float* o_g   = (const float*)d_in[21];
    const float* o_b   = (const float*)d_in[22];
    const float* o_tw2 = (const float*)d_in[23];
    const float* o_tb2 = (const float*)d_in[24];
    const float* ns_w  = (const float*)d_in[25];
    const float* ns_b  = (const float*)d_in[26];
    const float* nx_w  = (const float*)d_in[27];
    const float* nx_b  = (const float*)d_in[28];
    const float* no_w  = (const float*)d_in[29];
    const float* no_b  = (const float*)d_in[30];
    float* out = (float*)d_out;

    float *patchs, *patchx, *h1b, *q, *k, *v, *Wt, *att, *deb;
    cudaGetSymbolAddress((void**)&patchs, g_patchs);
    cudaGetSymbolAddress((void**)&patchx, g_patchx);
    cudaGetSymbolAddress((void**)&h1b,    g_h1b);
    cudaGetSymbolAddress((void**)&q,      g_q);
    cudaGetSymbolAddress((void**)&k,      g_k);
    cudaGetSymbolAddress((void**)&v,      g_v);
    cudaGetSymbolAddress((void**)&Wt,     g_Wt);
    cudaGetSymbolAddress((void**)&att,    g_att);
    cudaGetSymbolAddress((void**)&deb,    g_deb);

    static int fa_smem_set = 0;
    int fa_smem = 4 * 64 * FA_PAD * sizeof(float);
    if (!fa_smem_set) {
        cudaFuncSetAttribute(k_flash, cudaFuncAttributeMaxDynamicSharedMemorySize, fa_smem);
        fa_smem_set = 1;
    }

    k_patch<<<(NPATCH * 8 + 255) / 256, 256>>>(skip, ns_w, ns_b, patchs);
    k_patch<<<(NPATCH * 8 + 255) / 256, 256>>>(x,    nx_w, nx_b, patchx);

    const float* stem_patch[3] = {patchs, patchx, patchx};
    float* stem_out[3] = {q, k, v};
    int rope[3] = {1, 1, 0};
    for (int si = 0; si < 3; si++) {
        int base = 2 + si * 6;
        const float* w1 = (const float*)d_in[base + 0];
        const float* g1 = (const float*)d_in[base + 1];
        const float* b1 = (const float*)d_in[base + 2];
        const float* w2 = (const float*)d_in[base + 3];
        const float* g2 = (const float*)d_in[base + 4];
        const float* b2 = (const float*)d_in[base + 5];
        k_transW1<<<(192 * 48 + 255) / 256, 256>>>(w1, Wt);
        dim3 g1g(192 / 64, NPATCH / 64);
        k_gemm64<<<g1g, 256>>>(stem_patch[si], Wt, h1b, 48, 48, 192, 192);
        k_ln192gelu<<<NPATCH, 192>>>(h1b, g1, b1);
        k_transW2<<<(EE * KK2 + 255) / 256, 256>>>(w2, Wt);
        dim3 gg(EE / 128, NTOK / 64);
        k_mma_tf32<<<gg, 256>>>(h1b, Wt, stem_out[si], KK2, KK2, EE, EE);
        k_ln768<<<NTOK, 256>>>(stem_out[si], g2, b2, rope[si]);
    }

    k_flash<<<dim3(S12 / 64, B2 * NH), 256, fa_smem>>>(q, k, v, att);

    k_ln768<<<NTOK, 256>>>(att, no_w, no_b, 0);
    k_transWd<<<(EE * KK2 + 255) / 256, 256>>>(o_tw1, Wt);
    dim3 gd(KK2 / 128, NTOK / 64);
    k_mma_tf32<<<gd, 256>>>(att, Wt, deb, EE, EE, KK2, KK2);
    k_ln192gelu<<<NTOK * 8, 192>>>(deb, o_g, o_b);
    k_debed2<<<B2 * S24, 64>>>(deb, o_tw2, o_tb2, skip, out);
}

// round 11
// speedup vs baseline: 1.4270x; 1.4270x over previous
#include <cuda_runtime.h>
#include <cuda_fp16.h>
#include <math.h>
#include <stdint.h>

// ---------------- problem dims ----------------
#define B2   2
#define S48  110592   // 48^3
#define S24  13824    // 24^3
#define S12  1728     // 12^3
#define EE   768
#define NH   12
#define HD   64
#define NTOK (B2*S12)     // 3456
#define KK2  1536         // conv2 inner dim (192*8)
#define NPATCH (B2*S24)   // 27648 patch rows (= NTOK*8)

// ---------------- scratch ----------------
__device__ float g_patchs[NPATCH*48];
__device__ float g_patchx[NPATCH*48];
__device__ float g_h1b   [NPATCH*192];             // conv1 out == conv2 A [3456x1536]
__device__ float g_q     [NTOK*EE];
__device__ float g_k     [NTOK*EE];
__device__ float g_v     [NTOK*EE];
__device__ float g_Wt    [KK2*EE];                 // fp32 transposed weight scratch
__device__ float g_S     [(size_t)B2*NH*S12*S12];  // attention scores
__device__ float g_att   [NTOK*EE];
__device__ float g_deb   [NTOK*KK2];

// ---------------- block reductions ----------------
__device__ __forceinline__ float blk_sum(float v, float* sh) {
    int lane = threadIdx.x & 31;
#pragma unroll
    for (int o = 16; o; o >>= 1) v += __shfl_xor_sync(0xffffffffu, v, o);
    __syncthreads();
    if (lane == 0) sh[threadIdx.x >> 5] = v;
    __syncthreads();
    int nw = blockDim.x >> 5;
    v = (lane < nw) ? sh[lane] : 0.f;
#pragma unroll
    for (int o = 16; o; o >>= 1) v += __shfl_xor_sync(0xffffffffu, v, o);
    return v;
}
__device__ __forceinline__ float blk_max(float v, float* sh) {
    int lane = threadIdx.x & 31;
#pragma unroll
    for (int o = 16; o; o >>= 1) v = fmaxf(v, __shfl_xor_sync(0xffffffffu, v, o));
    __syncthreads();
    if (lane == 0) sh[threadIdx.x >> 5] = v;
    __syncthreads();
    int nw = blockDim.x >> 5;
    v = (lane < nw) ? sh[lane] : -3.4e38f;
#pragma unroll
    for (int o = 16; o; o >>= 1) v = fmaxf(v, __shfl_xor_sync(0xffffffffu, v, o));
    return v;
}

// robust fp32 sincos: Cody-Waite reduce mod 2pi, then accurate-range trig.
__device__ __forceinline__ void rope_trig(float f, float& cs, float& sn) {
    float n = rintf(f * 0.15915494309189535f);
    float r = fmaf(-n, 6.28125f, f);
    r = fmaf(-n, 1.9353071795864769e-3f, r);
    cs = cosf(r);
    sn = sinf(r);
}

// ---------------- fp16 split helpers ----------------
__device__ __forceinline__ uint32_t pack_h2(float a, float b) {
    __half2 h = __halves2half2(__float2half_rn(a), __float2half_rn(b));
    return *(uint32_t*)&h;
}
__device__ __forceinline__ void split_f16(float x, float& hi, float& lo) {
    __half h = __float2half_rn(x);
    hi = __half2float(h);
    lo = x - hi;
}
__device__ __forceinline__ void mma_f16(float* c, const uint32_t* a, const uint32_t* b) {
    asm volatile(
        "mma.sync.aligned.m16n8k16.row.col.f32.f16.f16.f32 "
        "{%0,%1,%2,%3}, {%4,%5,%6,%7}, {%8,%9}, {%0,%1,%2,%3};\n"
        : "+f"(c[0]), "+f"(c[1]), "+f"(c[2]), "+f"(c[3])
        : "r"(a[0]), "r"(a[1]), "r"(a[2]), "r"(a[3]), "r"(b[0]), "r"(b[1]));
}

// ---------------- fused LN6 + patch gather ----------------
__global__ void k_patch(const float* __restrict__ in, const float* __restrict__ w,
                        const float* __restrict__ bb, float* __restrict__ out) {
    int id = blockIdx.x * blockDim.x + threadIdx.x;
    if (id >= NPATCH * 8) return;
    int kpq = id & 7;
    int p = id >> 3;
    int bn = p / S24, pos = p - bn * S24;
    int h = pos / 576, w24 = (pos / 24) % 24, d = pos % 24;
    int k = kpq >> 2, pp = (kpq >> 1) & 1, qq = kpq & 1;
    size_t sp = ((size_t)(2 * h + k) * 48 + 2 * w24 + pp) * 48 + 2 * d + qq;
    const float* base = in + (size_t)bn * 6 * S48 + sp;
    float v[6], u = 0.f;
#pragma unroll
    for (int c = 0; c < 6; c++) { v[c] = base[(size_t)c * S48]; u += v[c]; }
    u *= (1.f / 6.f);
    float s = 0.f;
#pragma unroll
    for (int c = 0; c < 6; c++) { float dd = v[c] - u; s += dd * dd; }
    s *= (1.f / 6.f);
    float r = rsqrtf(s + 1e-6f);
    int token = bn * S12 + (h >> 1) * 144 + (w24 >> 1) * 12 + (d >> 1);
    int par = (h & 1) * 4 + (w24 & 1) * 2 + (d & 1);
    float* ob = out + ((size_t)token * 8 + par) * 48 + kpq;
#pragma unroll
    for (int c = 0; c < 6; c++) ob[c * 8] = (v[c] - u) * r * w[c] + bb[c];
}

// ---------------- small SGEMM (conv1 only): 64x64 tile ----------------
__global__ void k_gemm64(const float* __restrict__ A, const float* __restrict__ B,
                         float* __restrict__ C, int K, int lda, int ldb, int ldc) {
    __shared__ float As[16][64];
    __shared__ float Bs[16][64];
    int tid = threadIdx.x;
    int tx = tid & 15, ty = tid >> 4;
    int n0 = blockIdx.y * 64, m0 = blockIdx.x * 64;
    int lr = tid >> 2, lc = (tid & 3) * 4;
    int br = tid >> 4, bc = (tid & 15) * 4;
    const float* Ap = A + (size_t)(n0 + lr) * lda + lc;
    const float* Bp = B + (size_t)br * ldb + m0 + bc;
    float acc[4][4] = {};
    for (int k0 = 0; k0 < K; k0 += 16) {
        float4 a  = *(const float4*)(Ap + k0);
        float4 bv = *(const float4*)(Bp + (size_t)k0 * ldb);
        __syncthreads();
        As[lc + 0][lr] = a.x; As[lc + 1][lr] = a.y; As[lc + 2][lr] = a.z; As[lc + 3][lr] = a.w;
        *(float4*)&Bs[br][bc] = bv;
        __syncthreads();
#pragma unroll
        for (int kk = 0; kk < 16; kk++) {
            float4 av = *(const float4*)&As[kk][ty * 4];
            float4 bw = *(const float4*)&Bs[kk][tx * 4];
            float aa[4] = {av.x, av.y, av.z, av.w};
            float bbv[4] = {bw.x, bw.y, bw.z, bw.w};
#pragma unroll
            for (int i = 0; i < 4; i++)
#pragma unroll
                for (int j = 0; j < 4; j++) acc[i][j] += aa[i] * bbv[j];
        }
    }
#pragma unroll
    for (int i = 0; i < 4; i++) {
        float4 o = make_float4(acc[i][0], acc[i][1], acc[i][2], acc[i][3]);
        *(float4*)&C[(size_t)(n0 + ty * 4 + i) * ldc + m0 + tx * 4] = o;
    }
}

// ---------------- fp16x3 tensor-core GEMM (m16n8k16): C[n][m] = sum_k A[n][k]*B[k][m] ----
// block 256 thr, tile 64(rows) x 128(cols), k-step 16; warp tile 32x32.
// requires rows%64==0, cols%128==0, K%16==0.
#define AS_U 12     // uint32 (fp16x2) stride per A row (8 pairs used)
#define BS_U 136    // uint32 stride per B k-pair row (128 cols used)
__global__ __launch_bounds__(256, 2)
void k_mma_fp16(const float* __restrict__ A, const float* __restrict__ B,
                float* __restrict__ C, int K, int lda, int ldb, int ldc) {
    __shared__ uint32_t Ah[64 * AS_U], Al[64 * AS_U];
    __shared__ uint32_t Bh[8 * BS_U], Bl[8 * BS_U];
    int tid = threadIdx.x;
    int warp = tid >> 5, lane = tid & 31;
    int n0 = blockIdx.y * 64;
    int m0 = blockIdx.x * 128;
    int wm = (warp >> 2) * 32;
    int wn = (warp & 3) * 32;
    int ar = tid >> 2, ak4 = (tid & 3) * 4, ak2 = (tid & 3) * 2; // A loader
    int bk2 = tid >> 5, bm = (tid & 31) * 4;                     // B loader (k-pair rows)

    float acc[2][4][4] = {};

    for (int k0 = 0; k0 < K; k0 += 16) {
        __syncthreads();
        {
            float4 a = *(const float4*)&A[(size_t)(n0 + ar) * lda + k0 + ak4];
            float hx, lx, hy, ly, hz, lz, hw, lw;
            split_f16(a.x, hx, lx); split_f16(a.y, hy, ly);
            split_f16(a.z, hz, lz); split_f16(a.w, hw, lw);
            Ah[ar * AS_U + ak2]     = pack_h2(hx, hy);
            Ah[ar * AS_U + ak2 + 1] = pack_h2(hz, hw);
            Al[ar * AS_U + ak2]     = pack_h2(lx, ly);
            Al[ar * AS_U + ak2 + 1] = pack_h2(lz, lw);
            float4 b0 = *(const float4*)&B[(size_t)(k0 + 2 * bk2) * ldb + m0 + bm];
            float4 b1 = *(const float4*)&B[(size_t)(k0 + 2 * bk2 + 1) * ldb + m0 + bm];
            float b0v[4] = {b0.x, b0.y, b0.z, b0.w};
            float b1v[4] = {b1.x, b1.y, b1.z, b1.w};
#pragma unroll
            for (int j = 0; j < 4; j++) {
                float h0, l0, h1, l1;
                split_f16(b0v[j], h0, l0);
                split_f16(b1v[j], h1, l1);
                Bh[bk2 * BS_U + bm + j] = pack_h2(h0, h1);
                Bl[bk2 * BS_U + bm + j] = pack_h2(l0, l1);
            }
        }
        __syncthreads();

        uint32_t a_h[2][4], a_l[2][4];
        int r0 = wm + (lane >> 2);
        int kq = lane & 3;
#pragma unroll
        for (int ma = 0; ma < 2; ma++) {
            int r = r0 + ma * 16;
            a_h[ma][0] = Ah[r * AS_U + kq];
            a_h[ma][1] = Ah[(r + 8) * AS_U + kq];
            a_h[ma][2] = Ah[r * AS_U + kq + 4];
            a_h[ma][3] = Ah[(r + 8) * AS_U + kq + 4];
            a_l[ma][0] = Al[r * AS_U + kq];
            a_l[ma][1] = Al[(r + 8) * AS_U + kq];
            a_l[ma][2] = Al[r * AS_U + kq + 4];
            a_l[ma][3] = Al[(r + 8) * AS_U + kq + 4];
        }
        uint32_t b_h[4][2], b_l[4][2];
#pragma unroll
        for (int na = 0; na < 4; na++) {
            int c = wn + na * 8 + (lane >> 2);
            b_h[na][0] = Bh[kq * BS_U + c];
            b_h[na][1] = Bh[(kq + 4) * BS_U + c];
            b_l[na][0] = Bl[kq * BS_U + c];
            b_l[na][1] = Bl[(kq + 4) * BS_U + c];
        }
#pragma unroll
        for (int ma = 0; ma < 2; ma++)
#pragma unroll
            for (int na = 0; na < 4; na++) {
                mma_f16(acc[ma][na], a_h[ma], b_h[na]);
                mma_f16(acc[ma][na], a_l[ma], b_h[na]);
                mma_f16(acc[ma][na], a_h[ma], b_l[na]);
            }
    }

#pragma unroll
    for (int ma = 0; ma < 2; ma++) {
        int row = n0 + wm + ma * 16 + (lane >> 2);
#pragma unroll
        for (int na = 0; na < 4; na++) {
            int col = m0 + wn + na * 8 + (lane & 3) * 2;
            C[(size_t)row * ldc + col]           = acc[ma][na][0];
            C[(size_t)row * ldc + col + 1]       = acc[ma][na][1];
            C[(size_t)(row + 8) * ldc + col]     = acc[ma][na][2];
            C[(size_t)(row + 8) * ldc + col + 1] = acc[ma][na][3];
        }
    }
}

// ---------------- LN over 768 (+optional RoPE), in place ----------------
__global__ void k_ln768(float* __restrict__ X, const float* __restrict__ w,
                        const float* __restrict__ bb, int doRope) {
    __shared__ float s[768];
    __shared__ float sh[32];
    int n = blockIdx.x, tid = threadIdx.x;
    float* row = X + (size_t)n * 768;
    float partial = 0.f;
#pragma unroll
    for (int it = 0; it < 3; it++) { int j = tid + it * 256; float v = row[j]; s[j] = v; partial += v; }
    float u = blk_sum(partial, sh) * (1.f / 768.f);
    float p2 = 0.f;
#pragma unroll
    for (int it = 0; it < 3; it++) { int j = tid + it * 256; float dd = s[j] - u; p2 += dd * dd; }
    float var = blk_sum(p2, sh) * (1.f / 768.f);
    float rinv = rsqrtf(var + 1e-6f);
#pragma unroll
    for (int it = 0; it < 3; it++) { int j = tid + it * 256; s[j] = (s[j] - u) * rinv * w[j] + bb[j]; }
    __syncthreads();
    if (doRope) {
        int l = n % S12;
#pragma unroll
        for (int it = 0; it < 3; it++) {
            int j = tid + it * 256;
            int jm = (j < 384) ? j : j - 384;
            float inv = exp2f(-(float)jm * (13.287712379549449f / 384.f));
            float f = (float)l * inv;
            float cs, sn;
            rope_trig(f, cs, sn);
            float rot = (j < 384) ? -s[j + 384] : s[j - 384];
            row[j] = s[j] * cs + rot * sn;
        }
    } else {
#pragma unroll
        for (int it = 0; it < 3; it++) { int j = tid + it * 256; row[j] = s[j]; }
    }
}

// ---------------- attention scores ----------------
__global__ void k_scores(const float* __restrict__ Q, const float* __restrict__ Km,
                         float* __restrict__ S) {
    __shared__ float As[16][64];
    __shared__ float Bs[16][64];
    int z = blockIdx.z, b = z / NH, h = z - b * NH;
    int i0 = blockIdx.y * 64, j0 = blockIdx.x * 64;
    const float* qb = Q + (size_t)b * S12 * EE + h * HD;
    const float* kb = Km + (size_t)b * S12 * EE + h * HD;
    int tid = threadIdx.x;
    int tx = tid & 15, ty = tid >> 4;
    int lr = tid >> 2, lc = (tid & 3) * 4;
    float acc[4][4] = {};
    for (int k0 = 0; k0 < HD; k0 += 16) {
        float4 a  = *(const float4*)&qb[(size_t)(i0 + lr) * EE + k0 + lc];
        float4 bv = *(const float4*)&kb[(size_t)(j0 + lr) * EE + k0 + lc];
        __syncthreads();
        As[lc + 0][lr] = a.x;  As[lc + 1][lr] = a.y;  As[lc + 2][lr] = a.z;  As[lc + 3][lr] = a.w;
        Bs[lc + 0][lr] = bv.x; Bs[lc + 1][lr] = bv.y; Bs[lc + 2][lr] = bv.z; Bs[lc + 3][lr] = bv.w;
        __syncthreads();
#pragma unroll
        for (int kk = 0; kk < 16; kk++) {
            float4 av = *(const float4*)&As[kk][ty * 4];
            float4 bw = *(const float4*)&Bs[kk][tx * 4];
            float aa[4] = {av.x, av.y, av.z, av.w};
            float bbv[4] = {bw.x, bw.y, bw.z, bw.w};
#pragma unroll
            for (int i = 0; i < 4; i++)
#pragma unroll
                for (int j = 0; j < 4; j++) acc[i][j] += aa[i] * bbv[j];
        }
    }
    float* Sz = S + (size_t)z * S12 * S12;
#pragma unroll
    for (int i = 0; i < 4; i++) {
        float4 o = make_float4(acc[i][0], acc[i][1], acc[i][2], acc[i][3]);
        *(float4*)&Sz[(size_t)(i0 + ty * 4 + i) * S12 + j0 + tx * 4] = o;
    }
}

// ---------------- rowwise softmax with scale 1/8 (in place) ----------------
__global__ void k_softmax(float* __restrict__ S) {
    __shared__ float sh[32];
    int row = blockIdx.x;
    float* r = S + (size_t)row * S12;
    int tid = threadIdx.x;
    float vals[7];
    float mx = -3.4e38f;
    for (int i = 0, j = tid; j < S12; j += 256, i++) { float v = r[j]; vals[i] = v; mx = fmaxf(mx, v); }
    mx = blk_max(mx, sh);
    float sum = 0.f;
    for (int i = 0, j = tid; j < S12; j += 256, i++) {
        float e = expf((vals[i] - mx) * 0.125f);
        vals[i] = e; sum += e;
    }
    sum = blk_sum(sum, sh);
    float inv = 1.f / sum;
    for (int i = 0, j = tid; j < S12; j += 256, i++) r[j] = vals[i] * inv;
}

// ---------------- PV GEMM ----------------
__global__ void k_pv(const float* __restrict__ S, const float* __restrict__ V,
                     float* __restrict__ O) {
    __shared__ float As[16][64];
    __shared__ float Bs[16][64];
    int z = blockIdx.z, b = z / NH, h = z - b * NH;
    const float* A  = S + (size_t)z * S12 * S12;
    const float* Bm = V + (size_t)b * S12 * EE + h * HD;
    int n0 = blockIdx.y * 64;
    int tid = threadIdx.x, tx = tid & 15, ty = tid >> 4;
    int lr = tid >> 2, lc = (tid & 3) * 4;
    int br = tid >> 4, bc = (tid & 15) * 4;
    float acc[4][4] = {};
    for (int k0 = 0; k0 < S12; k0 += 16) {
        float4 a  = *(const float4*)&A[(size_t)(n0 + lr) * S12 + k0 + lc];
        float4 bv = *(const float4*)&Bm[(size_t)(k0 + br) * EE + bc];
        __syncthreads();
        As[lc + 0][lr] = a.x; As[lc + 1][lr] = a.y; As[lc + 2][lr] = a.z; As[lc + 3][lr] = a.w;
        *(float4*)&Bs[br][bc] = bv;
        __syncthreads();
#pragma unroll
        for (int kk = 0; kk < 16; kk++) {
            float4 av = *(const float4*)&As[kk][ty * 4];
            float4 bw = *(const float4*)&Bs[kk][tx * 4];
            float aa[4] = {av.x, av.y, av.z, av.w};
            float bbv[4] = {bw.x, bw.y, bw.z, bw.w};
#pragma unroll
            for (int i = 0; i < 4; i++)
#pragma unroll
                for (int j = 0; j < 4; j++) acc[i][j] += aa[i] * bbv[j];
        }
    }
#pragma unroll
    for (int i = 0; i < 4; i++)
#pragma unroll
        for (int j = 0; j < 4; j++)
            O[(size_t)(b * S12 + n0 + ty * 4 + i) * EE + (tx * 4 + j) * NH + h] = acc[i][j];
}

// ---------------- weight transposes ----------------
__global__ void k_transW1(const float* __restrict__ in, float* __restrict__ out) {
    int idx = blockIdx.x * blockDim.x + threadIdx.x;
    if (idx >= 192 * 48) return;
    int t = idx / 48, j = idx - t * 48;
    out[j * 192 + t] = in[idx];
}
__global__ void k_transW2(const float* __restrict__ in, float* __restrict__ out) {
    int idx = blockIdx.x * blockDim.x + threadIdx.x;
    if (idx >= EE * KK2) return;
    int o = idx / KK2, rest = idx - o * KK2;
    int t = rest >> 3, par = rest & 7;
    out[(size_t)(par * 192 + t) * EE + o] = in[idx];
}
__global__ void k_transWd(const float* __restrict__ in, float* __restrict__ out) {
    int idx = blockIdx.x * blockDim.x + threadIdx.x;
    if (idx >= EE * KK2) return;
    int i = idx / KK2, rest = idx - i * KK2;
    int o = rest >> 3, r = rest & 7;
    out[(size_t)i * KK2 + r * 192 + o] = in[idx];
}

// ---------------- LN192 + GELU rowwise, in place ----------------
__global__ void k_ln192gelu(float* __restrict__ X, const float* __restrict__ g,
                            const float* __restrict__ bb) {
    __shared__ float sh[32];
    int n = blockIdx.x, t = threadIdx.x;
    float* row = X + (size_t)n * 192;
    float v = row[t];
    float u = blk_sum(v, sh) * (1.f / 192.f);
    float dd = v - u;
    float var = blk_sum(dd * dd, sh) * (1.f / 192.f);
    float xn = dd * rsqrtf(var + 1e-6f) * g[t] + bb[t];
    row[t] = xn * normcdff(xn);
}

// ---------------- final convT2s2 (192->6) + bias + residual ----------------
__global__ void k_debed2(const float* __restrict__ glo, const float* __restrict__ W,
                         const float* __restrict__ bias, const float* __restrict__ res,
                         float* __restrict__ out) {
    __shared__ float row[192];
    int bid = blockIdx.x;
    int bn = bid / S24, pos = bid - bn * S24;
    int H = pos / 576, Wp = (pos / 24) % 24, D = pos % 24;
    int n1 = (H >> 1) * 144 + (Wp >> 1) * 12 + (D >> 1);
    int rr = (H & 1) * 4 + (Wp & 1) * 2 + (D & 1);
    const float* rp = glo + (size_t)(bn * S12 + n1) * KK2 + rr * 192;
    int t = threadIdx.x;
    for (int j = t; j < 192; j += 64) row[j] = rp[j];
    __syncthreads();
    if (t < 48) {
        int c = t >> 3, r2 = t & 7;
        float acc = 0.f;
#pragma unroll
        for (int o = 0; o < 192; o++) acc += row[o] * __ldg(&W[o * 48 + c * 8 + r2]);
        int Hf = 2 * H + (r2 >> 2), Wf = 2 * Wp + ((r2 >> 1) & 1), Df = 2 * D + (r2 & 1);
        size_t oi = (((size_t)(bn * 6 + c) * 48 + Hf) * 48 + Wf) * 48 + Df;
        out[oi] = acc + bias[c] + res[oi];
    }
}

// ---------------- launch ----------------
extern "C" void kernel_launch(void* const* d_in, const int* in_sizes, int n_in,
                              void* d_out, int out_size) {
    const float* x     = (const float*)d_in[0];
    const float* skip  = (const float*)d_in[1];
    const float* o_tw1 = (const float*)d_in[20];
    const float* o_g   = (const float*)d_in[21];
    const float* o_b   = (const float*)d_in[22];
    const float* o_tw2 = (const float*)d_in[23];
    const float* o_tb2 = (const float*)d_in[24];
    const float* ns_w  = (const float*)d_in[25];
    const float* ns_b  = (const float*)d_in[26];
    const float* nx_w  = (const float*)d_in[27];
    const float* nx_b  = (const float*)d_in[28];
    const float* no_w  = (const float*)d_in[29];
    const float* no_b  = (const float*)d_in[30];
    float* out = (float*)d_out;

    float *patchs, *patchx, *h1b, *q, *k, *v, *Wt, *S, *att, *deb;
    cudaGetSymbolAddress((void**)&patchs, g_patchs);
    cudaGetSymbolAddress((void**)&patchx, g_patchx);
    cudaGetSymbolAddress((void**)&h1b,    g_h1b);
    cudaGetSymbolAddress((void**)&q,      g_q);
    cudaGetSymbolAddress((void**)&k,      g_k);
    cudaGetSymbolAddress((void**)&v,      g_v);
    cudaGetSymbolAddress((void**)&Wt,     g_Wt);
    cudaGetSymbolAddress((void**)&S,      g_S);
    cudaGetSymbolAddress((void**)&att,    g_att);
    cudaGetSymbolAddress((void**)&deb,    g_deb);

    k_patch<<<(NPATCH * 8 + 255) / 256, 256>>>(skip, ns_w, ns_b, patchs);
    k_patch<<<(NPATCH * 8 + 255) / 256, 256>>>(x,    nx_w, nx_b, patchx);

    const float* stem_patch[3] = {patchs, patchx, patchx};
    float* stem_out[3] = {q, k, v};
    int rope[3] = {1, 1, 0};
    for (int si = 0; si < 3; si++) {
        int base = 2 + si * 6;
        const float* w1 = (const float*)d_in[base + 0];
        const float* g1 = (const float*)d_in[base + 1];
        const float* b1 = (const float*)d_in[base + 2];
        const float* w2 = (const float*)d_in[base + 3];
        const float* g2 = (const float*)d_in[base + 4];
        const float* b2 = (const float*)d_in[base + 5];
        k_transW1<<<(192 * 48 + 255) / 256, 256>>>(w1, Wt);
        dim3 g1g(192 / 64, NPATCH / 64);
        k_gemm64<<<g1g, 256>>>(stem_patch[si], Wt, h1b, 48, 48, 192, 192);
        k_ln192gelu<<<NPATCH, 192>>>(h1b, g1, b1);
        k_transW2<<<(EE * KK2 + 255) / 256, 256>>>(w2, Wt);
        dim3 gg(EE / 128, NTOK / 64);
        k_mma_fp16<<<gg, 256>>>(h1b, Wt, stem_out[si], KK2, KK2, EE, EE);
        k_ln768<<<NTOK, 256>>>(stem_out[si], g2, b2, rope[si]);
    }

    k_scores<<<dim3(27, 27, 24), 256>>>(q, k, S);
    k_softmax<<<B2 * NH * S12, 256>>>(S);
    k_pv<<<dim3(1, 27, 24), 256>>>(S, v, att);

    k_ln768<<<NTOK, 256>>>(att, no_w, no_b, 0);
    k_transWd<<<(EE * KK2 + 255) / 256, 256>>>(o_tw1, Wt);
    dim3 gd(KK2 / 128, NTOK / 64);
    k_mma_fp16<<<gd, 256>>>(att, Wt, deb, EE, EE, KK2, KK2);
    k_ln192gelu<<<NTOK * 8, 192>>>(deb, o_g, o_b);
    k_debed2<<<B2 * S24, 64>>>(deb, o_tw2, o_tb2, skip, out);
}